// round 4
// baseline (speedup 1.0000x reference)
#include <cuda_runtime.h>

#define TMAXB 100000

// Split accumulators:
//   g_hzNE[t] : sum of exp(lh) over NON-event samples (float, atomic add)
//   g_pk[t]   : packed event accumulator (one u64 atomic per event sample)
//     bits [0,8)   : m (event count, <=255, no carry: increments of 1)
//     bits [8,31)  : (lognom + 8*m) in fixed point 2^-12  (23 bits)
//     bits [31,64) : ties (sum exp over events) in fixed point 2^-17 (33 bits)
__device__ float              g_hzNE[TMAXB];
__device__ unsigned long long g_pk[TMAXB];
__device__ float              g_denom[TMAXB];   // suffix sum of (hzNE + ties)
__device__ double g_sum_terms;
__device__ double g_sum_lognom;
__device__ int    g_include;

#define L_SCALE 4096.0f        // 2^12
#define L_INV   (1.0f/4096.0f)
#define L_BIAS  8.0f
#define T_SCALE 131072.0f      // 2^17
#define T_INV   (1.0f/131072.0f)

// ---------------------------------------------------------------------------
__global__ void k_zero() {
    int i = blockIdx.x * blockDim.x + threadIdx.x;
    if (i < TMAXB) { g_hzNE[i] = 0.f; g_pk[i] = 0ull; }
    if (i == 0) { g_sum_terms = 0.0; g_sum_lognom = 0.0; g_include = 0; }
}

// ---------------------------------------------------------------------------
__device__ __forceinline__ void accum_one(float x, int t, int e) {
    float h = __expf(x);
    if (e) {
        long long fxT = __float2ll_rn(h * T_SCALE);
        long long fxL = __float2ll_rn((x + L_BIAS) * L_SCALE);
        unsigned long long p = ((unsigned long long)fxT << 31)
                             | ((unsigned long long)fxL << 8) | 1ull;
        atomicAdd(&g_pk[t], p);
    } else {
        atomicAdd(&g_hzNE[t], h);
    }
}

__global__ void k_accum(const float4* __restrict__ lh4,
                        const int4*   __restrict__ tt4,
                        const int4*   __restrict__ ev4, int n4) {
    int i = blockIdx.x * blockDim.x + threadIdx.x;
    int stride = gridDim.x * blockDim.x;
    for (; i < n4; i += stride) {
        float4 x = lh4[i];
        int4   t = tt4[i];
        int4   e = ev4[i];
        accum_one(x.x, t.x, e.x);
        accum_one(x.y, t.y, e.y);
        accum_one(x.z, t.z, e.z);
        accum_one(x.w, t.w, e.w);
    }
}

__global__ void k_accum_tail(const float* __restrict__ lh,
                             const int*   __restrict__ tt,
                             const int*   __restrict__ ev, int lo, int n) {
    int i = lo + blockIdx.x * blockDim.x + threadIdx.x;
    if (i < n) accum_one(lh[i], tt[i], ev[i]);
}

// ---------------------------------------------------------------------------
// Suffix sum over buckets of hz_t = hzNE_t + ties_t  -> g_denom.
#define SCAN_THREADS 1024
__device__ __forceinline__ float bucket_hz(int j) {
    unsigned long long p = g_pk[j];
    float T = (float)(p >> 31) * T_INV;
    return g_hzNE[j] + T;
}

__global__ void k_scan() {
    const int B = SCAN_THREADS;
    int tid = threadIdx.x;
    const int chunk = (TMAXB + B - 1) / B;  // 98
    int lo = tid * chunk;
    int hi = lo + chunk; if (hi > TMAXB) hi = TMAXB;
    if (lo > TMAXB) lo = TMAXB;

    float s = 0.f;
    for (int j = lo; j < hi; ++j) s += bucket_hz(j);

    __shared__ float sa[SCAN_THREADS];
    __shared__ float sb[SCAN_THREADS];
    sa[tid] = s;
    __syncthreads();
    float* src = sa; float* dst = sb;
    for (int off = 1; off < B; off <<= 1) {
        float v = src[tid];
        if (tid + off < B) v += src[tid + off];
        dst[tid] = v;
        __syncthreads();
        float* tmp = src; src = dst; dst = tmp;
    }
    float run = src[tid] - s;   // exclusive suffix (threads > tid)
    for (int j = hi - 1; j >= lo; --j) {
        run += bucket_hz(j);
        g_denom[j] = run;
    }
}

// ---------------------------------------------------------------------------
__device__ __forceinline__ double block_reduce_d(double v) {
    __shared__ double sh[32];
    int lane = threadIdx.x & 31, wid = threadIdx.x >> 5;
    #pragma unroll
    for (int o = 16; o > 0; o >>= 1)
        v += __shfl_down_sync(0xffffffffu, v, o);
    if (lane == 0) sh[wid] = v;
    __syncthreads();
    int nw = (blockDim.x + 31) >> 5;
    v = (threadIdx.x < nw) ? sh[threadIdx.x] : 0.0;
    if (wid == 0) {
        #pragma unroll
        for (int o = 16; o > 0; o >>= 1)
            v += __shfl_down_sync(0xffffffffu, v, o);
    }
    return v;
}

// ---------------------------------------------------------------------------
// Per-bucket Efron terms. Independent args via FMA (no serial chain),
// fold 4 factors per logf, accumulate logs in float (one double add per bucket).
__global__ void k_bucket() {
    int i = blockIdx.x * blockDim.x + threadIdx.x;
    double local_terms = 0.0;
    double local_lognom = 0.0;
    int cnt = 0;
    if (i < TMAXB) {
        unsigned long long p = g_pk[i];
        int m = (int)(p & 0xFFull);
        if (m > 0) {
            cnt = 1;
            float T = (float)(p >> 31) * T_INV;
            float L = (float)((p >> 8) & 0x7FFFFFull) * L_INV - L_BIAS * (float)m;
            local_lognom = (double)L;
            float D = g_denom[i];
            float step = T / (float)m;
            float lsum = 0.f;
            int l = 0;
            while (l < m) {
                int lim = (m - l) < 4 ? (m - l) : 4;
                float prod = 1.f;
                #pragma unroll 4
                for (int j = 0; j < lim; ++j)
                    prod *= fmaf(-(float)(l + j), step, D);
                lsum += logf(prod);
                l += lim;
            }
            local_terms = (double)lsum;
        }
    }
    double t_terms = block_reduce_d(local_terms);
    double t_logn  = block_reduce_d(local_lognom);
    double t_cnt   = block_reduce_d((double)cnt);
    if (threadIdx.x == 0) {
        if (t_terms != 0.0) atomicAdd(&g_sum_terms, t_terms);
        if (t_logn  != 0.0) atomicAdd(&g_sum_lognom, t_logn);
        int ic = (int)(t_cnt + 0.5);
        if (ic) atomicAdd(&g_include, ic);
    }
}

// ---------------------------------------------------------------------------
__global__ void k_final(float* out) {
    double pll = g_sum_lognom - g_sum_terms;
    out[0] = (float)(-(pll / (double)g_include));
}

// ---------------------------------------------------------------------------
extern "C" void kernel_launch(void* const* d_in, const int* in_sizes, int n_in,
                              void* d_out, int out_size) {
    const float* lh = (const float*)d_in[0];
    const int*   tt = (const int*)d_in[1];
    const int*   ev = (const int*)d_in[2];
    float* out = (float*)d_out;
    int n = in_sizes[0];
    int n4 = n / 4;
    int tail = n - n4 * 4;

    k_zero<<<(TMAXB + 255) / 256, 256>>>();

    k_accum<<<2048, 256>>>((const float4*)lh, (const int4*)tt, (const int4*)ev, n4);
    if (tail > 0)
        k_accum_tail<<<1, 256>>>(lh, tt, ev, n4 * 4, n);

    k_scan<<<1, SCAN_THREADS>>>();

    k_bucket<<<(TMAXB + 255) / 256, 256>>>();

    k_final<<<1, 1>>>(out);
}

// round 5
// speedup vs baseline: 1.3661x; 1.3661x over previous
#include <cuda_runtime.h>

#define TMAXB 100000

// AoS per-bucket accumulators: {x=hz sum, y=ties sum, z=lognom sum, w=event count}
__device__ float4 g_b[TMAXB];          // 1.6 MB, L2-resident
__device__ float  g_denom[TMAXB];      // suffix sum of hz (risk set)
__device__ double g_sum_terms;
__device__ double g_sum_lognom;
__device__ int    g_include;

// ---------------------------------------------------------------------------
__global__ void k_zero() {
    int i = blockIdx.x * blockDim.x + threadIdx.x;
    if (i < TMAXB) g_b[i] = make_float4(0.f, 0.f, 0.f, 0.f);
    if (i == 0) { g_sum_terms = 0.0; g_sum_lognom = 0.0; g_include = 0; }
}

// ---------------------------------------------------------------------------
__device__ __forceinline__ void red_v4(float4* p, float a, float b, float c, float d) {
    asm volatile("red.global.add.v4.f32 [%0], {%1,%2,%3,%4};"
                 :: "l"(p), "f"(a), "f"(b), "f"(c), "f"(d) : "memory");
}
__device__ __forceinline__ void red_f32(float* p, float a) {
    asm volatile("red.global.add.f32 [%0], %1;"
                 :: "l"(p), "f"(a) : "memory");
}

// Non-events touch only .x (scalar red). Events do the full v4 red.
__device__ __forceinline__ void accum_one(float x, int t, int e) {
    float h = __expf(x);
    if (e)
        red_v4(&g_b[t], h, h, x, 1.0f);
    else
        red_f32(&g_b[t].x, h);
}

__global__ void k_accum(const float4* __restrict__ lh4,
                        const int4*   __restrict__ tt4,
                        const int4*   __restrict__ ev4, int n4) {
    int i = blockIdx.x * blockDim.x + threadIdx.x;
    int stride = gridDim.x * blockDim.x;
    for (; i < n4; i += stride) {
        float4 x = lh4[i];
        int4   t = tt4[i];
        int4   e = ev4[i];
        accum_one(x.x, t.x, e.x);
        accum_one(x.y, t.y, e.y);
        accum_one(x.z, t.z, e.z);
        accum_one(x.w, t.w, e.w);
    }
}

__global__ void k_accum_tail(const float* __restrict__ lh,
                             const int*   __restrict__ tt,
                             const int*   __restrict__ ev, int lo, int n) {
    int i = lo + blockIdx.x * blockDim.x + threadIdx.x;
    if (i < n) accum_one(lh[i], tt[i], ev[i]);
}

// ---------------------------------------------------------------------------
// Suffix sum of g_b[].x -> g_denom. Single block, chunked.
#define SCAN_THREADS 1024
__global__ void k_scan() {
    const int B = SCAN_THREADS;
    int tid = threadIdx.x;
    const int chunk = (TMAXB + B - 1) / B;  // 98
    int lo = tid * chunk;
    int hi = lo + chunk; if (hi > TMAXB) hi = TMAXB;
    if (lo > TMAXB) lo = TMAXB;

    float s = 0.f;
    for (int j = lo; j < hi; ++j) s += g_b[j].x;

    __shared__ float sa[SCAN_THREADS];
    __shared__ float sb[SCAN_THREADS];
    sa[tid] = s;
    __syncthreads();
    float* src = sa; float* dst = sb;
    for (int off = 1; off < B; off <<= 1) {
        float v = src[tid];
        if (tid + off < B) v += src[tid + off];
        dst[tid] = v;
        __syncthreads();
        float* tmp = src; src = dst; dst = tmp;
    }
    float run = src[tid] - s;   // exclusive suffix (threads > tid)
    for (int j = hi - 1; j >= lo; --j) {
        run += g_b[j].x;
        g_denom[j] = run;
    }
}

// ---------------------------------------------------------------------------
__device__ __forceinline__ double block_reduce_d(double v) {
    __shared__ double sh[32];
    int lane = threadIdx.x & 31, wid = threadIdx.x >> 5;
    #pragma unroll
    for (int o = 16; o > 0; o >>= 1)
        v += __shfl_down_sync(0xffffffffu, v, o);
    if (lane == 0) sh[wid] = v;
    __syncthreads();
    int nw = (blockDim.x + 31) >> 5;
    v = (threadIdx.x < nw) ? sh[threadIdx.x] : 0.0;
    if (wid == 0) {
        #pragma unroll
        for (int o = 16; o > 0; o >>= 1)
            v += __shfl_down_sync(0xffffffffu, v, o);
    }
    return v;
}

// ---------------------------------------------------------------------------
// Per-bucket Efron terms: independent FMA args, fold 4 factors per logf,
// float log accumulation (one double add per bucket).
__global__ void k_bucket() {
    int i = blockIdx.x * blockDim.x + threadIdx.x;
    double local_terms = 0.0;
    double local_lognom = 0.0;
    int cnt = 0;
    if (i < TMAXB) {
        float4 b = g_b[i];
        int m = (int)(b.w + 0.5f);
        if (m > 0) {
            cnt = 1;
            local_lognom = (double)b.z;
            float D = g_denom[i];
            float step = b.y / (float)m;
            float lsum = 0.f;
            int l = 0;
            while (l < m) {
                int lim = (m - l) < 4 ? (m - l) : 4;
                float prod = 1.f;
                #pragma unroll 4
                for (int j = 0; j < lim; ++j)
                    prod *= fmaf(-(float)(l + j), step, D);
                lsum += logf(prod);
                l += lim;
            }
            local_terms = (double)lsum;
        }
    }
    double t_terms = block_reduce_d(local_terms);
    double t_logn  = block_reduce_d(local_lognom);
    double t_cnt   = block_reduce_d((double)cnt);
    if (threadIdx.x == 0) {
        if (t_terms != 0.0) atomicAdd(&g_sum_terms, t_terms);
        if (t_logn  != 0.0) atomicAdd(&g_sum_lognom, t_logn);
        int ic = (int)(t_cnt + 0.5);
        if (ic) atomicAdd(&g_include, ic);
    }
}

// ---------------------------------------------------------------------------
__global__ void k_final(float* out) {
    double pll = g_sum_lognom - g_sum_terms;
    out[0] = (float)(-(pll / (double)g_include));
}

// ---------------------------------------------------------------------------
extern "C" void kernel_launch(void* const* d_in, const int* in_sizes, int n_in,
                              void* d_out, int out_size) {
    const float* lh = (const float*)d_in[0];
    const int*   tt = (const int*)d_in[1];
    const int*   ev = (const int*)d_in[2];
    float* out = (float*)d_out;
    int n = in_sizes[0];
    int n4 = n / 4;
    int tail = n - n4 * 4;

    k_zero<<<(TMAXB + 255) / 256, 256>>>();

    k_accum<<<2048, 256>>>((const float4*)lh, (const int4*)tt, (const int4*)ev, n4);
    if (tail > 0)
        k_accum_tail<<<1, 256>>>(lh, tt, ev, n4 * 4, n);

    k_scan<<<1, SCAN_THREADS>>>();

    k_bucket<<<(TMAXB + 255) / 256, 256>>>();

    k_final<<<1, 1>>>(out);
}

// round 6
// speedup vs baseline: 3.7854x; 2.7708x over previous
#include <cuda_runtime.h>

#define TMAXB 100000
#define TILE  1024
#define NT    ((TMAXB + TILE - 1) / TILE)   // 98

// AoS per-bucket accumulators: {x=hz sum, y=ties sum, z=lognom sum, w=event count}
__device__ float4 g_b[TMAXB];                       // 1.6 MB, L2-resident
__device__ __align__(16) float g_denom[TMAXB];      // suffix sum of hz (risk set)
__device__ float  g_part[NT];                       // per-tile totals
__device__ float  g_ptsuf[NT];                      // exclusive suffix of tile totals
__device__ double g_sum_terms;
__device__ double g_sum_lognom;
__device__ int    g_include;

// ---------------------------------------------------------------------------
__global__ void k_zero() {
    int i = blockIdx.x * blockDim.x + threadIdx.x;
    if (i < TMAXB) g_b[i] = make_float4(0.f, 0.f, 0.f, 0.f);
    if (i == 0) { g_sum_terms = 0.0; g_sum_lognom = 0.0; g_include = 0; }
}

// ---------------------------------------------------------------------------
__device__ __forceinline__ void red_v4(float4* p, float a, float b, float c, float d) {
    asm volatile("red.global.add.v4.f32 [%0], {%1,%2,%3,%4};"
                 :: "l"(p), "f"(a), "f"(b), "f"(c), "f"(d) : "memory");
}
__device__ __forceinline__ void red_f32(float* p, float a) {
    asm volatile("red.global.add.f32 [%0], %1;"
                 :: "l"(p), "f"(a) : "memory");
}

__device__ __forceinline__ void accum_one(float x, int t, int e) {
    float h = __expf(x);
    if (e)
        red_v4(&g_b[t], h, h, x, 1.0f);
    else
        red_f32(&g_b[t].x, h);
}

__global__ void k_accum(const float4* __restrict__ lh4,
                        const int4*   __restrict__ tt4,
                        const int4*   __restrict__ ev4, int n4) {
    int i = blockIdx.x * blockDim.x + threadIdx.x;
    int stride = gridDim.x * blockDim.x;
    for (; i < n4; i += stride) {
        float4 x = lh4[i];
        int4   t = tt4[i];
        int4   e = ev4[i];
        accum_one(x.x, t.x, e.x);
        accum_one(x.y, t.y, e.y);
        accum_one(x.z, t.z, e.z);
        accum_one(x.w, t.w, e.w);
    }
}

__global__ void k_accum_tail(const float* __restrict__ lh,
                             const int*   __restrict__ tt,
                             const int*   __restrict__ ev, int lo, int n) {
    int i = lo + blockIdx.x * blockDim.x + threadIdx.x;
    if (i < n) accum_one(lh[i], tt[i], ev[i]);
}

// ---------------------------------------------------------------------------
__device__ __forceinline__ float block_reduce_f(float v) {
    __shared__ float sh[32];
    int lane = threadIdx.x & 31, wid = threadIdx.x >> 5;
    #pragma unroll
    for (int o = 16; o > 0; o >>= 1)
        v += __shfl_down_sync(0xffffffffu, v, o);
    if (lane == 0) sh[wid] = v;
    __syncthreads();
    int nw = (blockDim.x + 31) >> 5;
    v = (threadIdx.x < nw) ? sh[threadIdx.x] : 0.f;
    if (wid == 0) {
        #pragma unroll
        for (int o = 16; o > 0; o >>= 1)
            v += __shfl_down_sync(0xffffffffu, v, o);
    }
    return v;
}

// Scan phase A: per-tile totals (coalesced reads of g_b[].x)
__global__ void k_scan_part() {
    int b = blockIdx.x;
    int base = b * TILE;
    float s = 0.f;
    #pragma unroll
    for (int k = 0; k < 4; ++k) {
        int j = base + threadIdx.x + k * 256;
        if (j < TMAXB) s += g_b[j].x;
    }
    s = block_reduce_f(s);
    if (threadIdx.x == 0) g_part[b] = s;
}

// Scan phase B: exclusive suffix scan of the NT tile totals (1 block)
__global__ void k_scan_tops() {
    __shared__ float s[128];
    int tid = threadIdx.x;
    float v = (tid < NT) ? g_part[tid] : 0.f;
    s[tid] = v;
    __syncthreads();
    for (int off = 1; off < 128; off <<= 1) {
        float a = s[tid] + ((tid + off < 128) ? s[tid + off] : 0.f);
        __syncthreads();
        s[tid] = a;
        __syncthreads();
    }
    if (tid < NT) g_ptsuf[tid] = s[tid] - v;   // exclusive: tiles > tid
}

// Scan phase C: per-tile suffix scan, coalesced via smem, float4 writes
__global__ void k_scan_apply() {
    __shared__ float s[TILE];
    __shared__ float ts[256];
    int b = blockIdx.x, tid = threadIdx.x;
    int base = b * TILE;
    #pragma unroll
    for (int k = 0; k < 4; ++k) {
        int j = base + tid + k * 256;
        s[tid + k * 256] = (j < TMAXB) ? g_b[j].x : 0.f;
    }
    __syncthreads();
    int lo = tid * 4;
    float4 v = *(const float4*)&s[lo];
    float tsum = v.x + v.y + v.z + v.w;
    ts[tid] = tsum;
    __syncthreads();
    for (int off = 1; off < 256; off <<= 1) {
        float a = ts[tid] + ((tid + off < 256) ? ts[tid + off] : 0.f);
        __syncthreads();
        ts[tid] = a;
        __syncthreads();
    }
    float run = ts[tid] - tsum + g_ptsuf[b];   // everything after this chunk
    float o3 = v.w + run;
    float o2 = v.z + o3;
    float o1 = v.y + o2;
    float o0 = v.x + o1;
    int j = base + lo;
    if (j + 3 < TMAXB) {
        *(float4*)&g_denom[j] = make_float4(o0, o1, o2, o3);
    } else {
        if (j     < TMAXB) g_denom[j]     = o0;
        if (j + 1 < TMAXB) g_denom[j + 1] = o1;
        if (j + 2 < TMAXB) g_denom[j + 2] = o2;
        if (j + 3 < TMAXB) g_denom[j + 3] = o3;
    }
}

// ---------------------------------------------------------------------------
__device__ __forceinline__ double block_reduce_d(double v) {
    __shared__ double sh[32];
    int lane = threadIdx.x & 31, wid = threadIdx.x >> 5;
    #pragma unroll
    for (int o = 16; o > 0; o >>= 1)
        v += __shfl_down_sync(0xffffffffu, v, o);
    if (lane == 0) sh[wid] = v;
    __syncthreads();
    int nw = (blockDim.x + 31) >> 5;
    v = (threadIdx.x < nw) ? sh[threadIdx.x] : 0.0;
    if (wid == 0) {
        #pragma unroll
        for (int o = 16; o > 0; o >>= 1)
            v += __shfl_down_sync(0xffffffffu, v, o);
    }
    return v;
}

// ---------------------------------------------------------------------------
// Per-bucket Efron terms: independent FMA args, fold 4 factors per __logf,
// float log accumulation (one double add per bucket).
__global__ void k_bucket() {
    int i = blockIdx.x * blockDim.x + threadIdx.x;
    double local_terms = 0.0;
    double local_lognom = 0.0;
    int cnt = 0;
    if (i < TMAXB) {
        float4 b = g_b[i];
        int m = (int)(b.w + 0.5f);
        if (m > 0) {
            cnt = 1;
            local_lognom = (double)b.z;
            float D = g_denom[i];
            float step = b.y / (float)m;
            float lsum = 0.f;
            int l = 0;
            while (l < m) {
                int lim = (m - l) < 4 ? (m - l) : 4;
                float prod = 1.f;
                #pragma unroll 4
                for (int j = 0; j < lim; ++j)
                    prod *= fmaf(-(float)(l + j), step, D);
                lsum += __logf(prod);
                l += lim;
            }
            local_terms = (double)lsum;
        }
    }
    double t_terms = block_reduce_d(local_terms);
    double t_logn  = block_reduce_d(local_lognom);
    double t_cnt   = block_reduce_d((double)cnt);
    if (threadIdx.x == 0) {
        if (t_terms != 0.0) atomicAdd(&g_sum_terms, t_terms);
        if (t_logn  != 0.0) atomicAdd(&g_sum_lognom, t_logn);
        int ic = (int)(t_cnt + 0.5);
        if (ic) atomicAdd(&g_include, ic);
    }
}

// ---------------------------------------------------------------------------
__global__ void k_final(float* out) {
    double pll = g_sum_lognom - g_sum_terms;
    out[0] = (float)(-(pll / (double)g_include));
}

// ---------------------------------------------------------------------------
extern "C" void kernel_launch(void* const* d_in, const int* in_sizes, int n_in,
                              void* d_out, int out_size) {
    const float* lh = (const float*)d_in[0];
    const int*   tt = (const int*)d_in[1];
    const int*   ev = (const int*)d_in[2];
    float* out = (float*)d_out;
    int n = in_sizes[0];
    int n4 = n / 4;
    int tail = n - n4 * 4;

    k_zero<<<(TMAXB + 255) / 256, 256>>>();

    k_accum<<<2048, 256>>>((const float4*)lh, (const int4*)tt, (const int4*)ev, n4);
    if (tail > 0)
        k_accum_tail<<<1, 256>>>(lh, tt, ev, n4 * 4, n);

    k_scan_part<<<NT, 256>>>();
    k_scan_tops<<<1, 128>>>();
    k_scan_apply<<<NT, 256>>>();

    k_bucket<<<(TMAXB + 255) / 256, 256>>>();

    k_final<<<1, 1>>>(out);
}

// round 7
// speedup vs baseline: 4.0650x; 1.0739x over previous
#include <cuda_runtime.h>

#define TMAXB 100000
#define TILE  256
#define NT    ((TMAXB + TILE - 1) / TILE)   // 391

// AoS per-bucket accumulators: {x=hz sum, y=ties sum, z=lognom sum, w=event count}
// Zero-initialized at module load; every kernel_launch leaves them zeroed again
// (k_fused re-zeros g_b, k_final re-zeros the scalars), so no k_zero pass.
__device__ float4 g_b[TMAXB];          // 1.6 MB, L2-resident
__device__ float  g_part[NT];          // per-tile totals of hz
__device__ double g_sum_terms;
__device__ double g_sum_lognom;
__device__ int    g_include;

// ---------------------------------------------------------------------------
__device__ __forceinline__ void red_v4(float4* p, float a, float b, float c, float d) {
    asm volatile("red.global.add.v4.f32 [%0], {%1,%2,%3,%4};"
                 :: "l"(p), "f"(a), "f"(b), "f"(c), "f"(d) : "memory");
}
__device__ __forceinline__ void red_f32(float* p, float a) {
    asm volatile("red.global.add.f32 [%0], %1;"
                 :: "l"(p), "f"(a) : "memory");
}

__device__ __forceinline__ void accum_one(float x, int t, int e) {
    float h = __expf(x);
    if (e)
        red_v4(&g_b[t], h, h, x, 1.0f);
    else
        red_f32(&g_b[t].x, h);
}

__global__ void k_accum(const float4* __restrict__ lh4,
                        const int4*   __restrict__ tt4,
                        const int4*   __restrict__ ev4, int n4) {
    int i = blockIdx.x * blockDim.x + threadIdx.x;
    int stride = gridDim.x * blockDim.x;
    for (; i < n4; i += stride) {
        float4 x = lh4[i];
        int4   t = tt4[i];
        int4   e = ev4[i];
        accum_one(x.x, t.x, e.x);
        accum_one(x.y, t.y, e.y);
        accum_one(x.z, t.z, e.z);
        accum_one(x.w, t.w, e.w);
    }
}

__global__ void k_accum_tail(const float* __restrict__ lh,
                             const int*   __restrict__ tt,
                             const int*   __restrict__ ev, int lo, int n) {
    int i = lo + blockIdx.x * blockDim.x + threadIdx.x;
    if (i < n) accum_one(lh[i], tt[i], ev[i]);
}

// ---------------------------------------------------------------------------
__device__ __forceinline__ float block_reduce_f(float v) {
    __shared__ float sh[8];
    int lane = threadIdx.x & 31, wid = threadIdx.x >> 5;
    #pragma unroll
    for (int o = 16; o > 0; o >>= 1)
        v += __shfl_down_sync(0xffffffffu, v, o);
    if (lane == 0) sh[wid] = v;
    __syncthreads();
    v = (threadIdx.x < 8) ? sh[threadIdx.x] : 0.f;
    if (wid == 0) {
        #pragma unroll
        for (int o = 4; o > 0; o >>= 1)
            v += __shfl_down_sync(0xffffffffu, v, o);
    }
    return v;   // valid in thread 0
}

__device__ __forceinline__ double block_reduce_d(double v) {
    __shared__ double sh[8];
    int lane = threadIdx.x & 31, wid = threadIdx.x >> 5;
    #pragma unroll
    for (int o = 16; o > 0; o >>= 1)
        v += __shfl_down_sync(0xffffffffu, v, o);
    if (lane == 0) sh[wid] = v;
    __syncthreads();
    v = (threadIdx.x < 8) ? sh[threadIdx.x] : 0.0;
    if (wid == 0) {
        #pragma unroll
        for (int o = 4; o > 0; o >>= 1)
            v += __shfl_down_sync(0xffffffffu, v, o);
    }
    return v;
}

// ---------------------------------------------------------------------------
// Per-tile totals of hz (coalesced reads of g_b[].x)
__global__ void k_part() {
    int b = blockIdx.x;
    int i = b * TILE + threadIdx.x;
    float s = (i < TMAXB) ? g_b[i].x : 0.f;
    s = block_reduce_f(s);
    if (threadIdx.x == 0) g_part[b] = s;
}

// ---------------------------------------------------------------------------
// Fused: per-block (tile of 256 buckets):
//   1) exclusive suffix of tile totals (masked reduce over g_part)
//   2) in-tile suffix scan of hz -> per-bucket risk-set denom D
//   3) Efron terms per bucket (fold 4 factors per __logf)
//   4) re-zero g_b tile for the next replay
__global__ void k_fused() {
    __shared__ float sa[TILE];
    __shared__ float sb[TILE];
    __shared__ float s_sfx;
    int b = blockIdx.x, tid = threadIdx.x;
    int i = b * TILE + tid;

    // (1) sum of g_part[j] for j > b
    float acc = 0.f;
    for (int j = tid; j < NT; j += TILE)
        if (j > b) acc += g_part[j];
    acc = block_reduce_f(acc);
    if (tid == 0) s_sfx = acc;

    // (2) inclusive suffix scan of tile hz
    float4 bv = (i < TMAXB) ? g_b[i] : make_float4(0.f, 0.f, 0.f, 0.f);
    if (i < TMAXB) g_b[i] = make_float4(0.f, 0.f, 0.f, 0.f);   // (4) self-clean
    sa[tid] = bv.x;
    __syncthreads();
    float* src = sa; float* dst = sb;
    #pragma unroll
    for (int off = 1; off < TILE; off <<= 1) {
        float v = src[tid];
        if (tid + off < TILE) v += src[tid + off];
        dst[tid] = v;
        __syncthreads();
        float* tmp = src; src = dst; dst = tmp;
    }
    float D = src[tid] + s_sfx;   // risk-set sum for bucket i

    // (3) Efron terms
    double local_terms = 0.0, local_lognom = 0.0;
    int cnt = 0;
    int m = (int)(bv.w + 0.5f);
    if (i < TMAXB && m > 0) {
        cnt = 1;
        local_lognom = (double)bv.z;
        float step = bv.y / (float)m;
        float lsum = 0.f;
        int l = 0;
        while (l < m) {
            int lim = (m - l) < 4 ? (m - l) : 4;
            float prod = 1.f;
            #pragma unroll 4
            for (int j = 0; j < lim; ++j)
                prod *= fmaf(-(float)(l + j), step, D);
            lsum += __logf(prod);
            l += lim;
        }
        local_terms = (double)lsum;
    }
    double t_terms = block_reduce_d(local_terms);
    __syncthreads();
    double t_logn  = block_reduce_d(local_lognom);
    __syncthreads();
    double t_cnt   = block_reduce_d((double)cnt);
    if (tid == 0) {
        if (t_terms != 0.0) atomicAdd(&g_sum_terms, t_terms);
        if (t_logn  != 0.0) atomicAdd(&g_sum_lognom, t_logn);
        int ic = (int)(t_cnt + 0.5);
        if (ic) atomicAdd(&g_include, ic);
    }
}

// ---------------------------------------------------------------------------
__global__ void k_final(float* out) {
    double pll = g_sum_lognom - g_sum_terms;
    out[0] = (float)(-(pll / (double)g_include));
    // self-clean for next replay
    g_sum_terms = 0.0;
    g_sum_lognom = 0.0;
    g_include = 0;
}

// ---------------------------------------------------------------------------
extern "C" void kernel_launch(void* const* d_in, const int* in_sizes, int n_in,
                              void* d_out, int out_size) {
    const float* lh = (const float*)d_in[0];
    const int*   tt = (const int*)d_in[1];
    const int*   ev = (const int*)d_in[2];
    float* out = (float*)d_out;
    int n = in_sizes[0];
    int n4 = n / 4;
    int tail = n - n4 * 4;

    k_accum<<<2048, 256>>>((const float4*)lh, (const int4*)tt, (const int4*)ev, n4);
    if (tail > 0)
        k_accum_tail<<<1, 256>>>(lh, tt, ev, n4 * 4, n);

    k_part<<<NT, TILE>>>();
    k_fused<<<NT, TILE>>>();
    k_final<<<1, 1>>>(out);
}